// round 13
// baseline (speedup 1.0000x reference)
#include <cuda_runtime.h>
#include <cuda_fp16.h>
#include <mma.h>

using namespace nvcuda;

// Problem constants
constexpr int T_ = 4;
constexpr int B_ = 16;
constexpr int C_ = 512;
constexpr int N_ = 256;                // H*W
constexpr int S_ = B_ * C_ * N_;       // per-timestep elements
constexpr int TOT_ = T_ * S_;

constexpr int CH_ = 4;                 // batches per pipeline chunk
constexpr int NCHUNK_ = B_ / CH_;      // 4 chunks

// GEMM tiling: block 128x128x32, 4 warps, warp tile 64x64, fp16 operands
constexpr int BM = 128, BN = 128, BK = 32;
constexpr int ASTRH = 40;    // half stride; 80B = 5*16
constexpr int BSTRH = 136;   // 272B = 17*16
constexpr int CSTR = 132;    // float stride for epilogue staging
constexpr int PIPE_BYTES = 2 * (BM * ASTRH + BK * BSTRH) * 2;
constexpr int EPI_BYTES = BM * CSTR * 4;
constexpr int SMEM_BYTES = (PIPE_BYTES > EPI_BYTES) ? PIPE_BYTES : EPI_BYTES;

// Scratch (device globals: allocation-free rule)
__device__ __align__(16) __half g_wq[C_ * C_];
__device__ __align__(16) __half g_wk[C_ * C_];
__device__ __align__(16) __half g_wv[C_ * C_];
__device__ __align__(16) __half g_wp[C_ * C_];
__device__ float g_sq[C_];
__device__ float g_sk[C_];
__device__ float g_sv[C_];
__device__ float g_sp[C_];
__device__ __align__(16) __half g_xs[TOT_];          // input spikes
__device__ __align__(16) float g_q[TOT_];            // q pre-activations (fp32)
__device__ __align__(16) float g_k[TOT_];
__device__ __align__(16) float g_v[TOT_];
__device__ __align__(16) __half g_attn[TOT_];        // attn = q_spike * kv_spike (fp16)

// ---------------------------------------------------------------------------
// cp.async helpers
// ---------------------------------------------------------------------------
__device__ __forceinline__ void cp16(void* dst, const void* src) {
    unsigned s = (unsigned)__cvta_generic_to_shared(dst);
    asm volatile("cp.async.cg.shared.global [%0], [%1], 16;\n" :: "r"(s), "l"(src));
}
#define CP_COMMIT() asm volatile("cp.async.commit_group;\n" ::: "memory")
#define CP_WAIT0()  asm volatile("cp.async.wait_group 0;\n" ::: "memory")

// ---------------------------------------------------------------------------
// Prep: fold BN scale into weights (fp16); per-channel shifts (fp32).
// ---------------------------------------------------------------------------
__global__ void prep_kernel(
    const float* __restrict__ qw, const float* __restrict__ qg, const float* __restrict__ qb,
    const float* __restrict__ qm, const float* __restrict__ qvv,
    const float* __restrict__ kw, const float* __restrict__ kg, const float* __restrict__ kb,
    const float* __restrict__ km, const float* __restrict__ kvv,
    const float* __restrict__ vw, const float* __restrict__ vg, const float* __restrict__ vb,
    const float* __restrict__ vm, const float* __restrict__ vvv,
    const float* __restrict__ pw, const float* __restrict__ pb, const float* __restrict__ pg,
    const float* __restrict__ pb2, const float* __restrict__ pm, const float* __restrict__ pvv)
{
    int idx = blockIdx.x * blockDim.x + threadIdx.x;
    if (idx >= C_ * C_) return;
    int o = idx >> 9;
    float invq = qg[o] / sqrtf(qvv[o] + 1e-5f);
    float invk = kg[o] / sqrtf(kvv[o] + 1e-5f);
    float invv = vg[o] / sqrtf(vvv[o] + 1e-5f);
    float invp = pg[o] / sqrtf(pvv[o] + 1e-5f);
    g_wq[idx] = __float2half_rn(qw[idx] * invq);
    g_wk[idx] = __float2half_rn(kw[idx] * invk);
    g_wv[idx] = __float2half_rn(vw[idx] * invv);
    g_wp[idx] = __float2half_rn(pw[idx] * invp);
    if ((idx & 511) == 0) {
        g_sq[o] = qb[o] - qm[o] * invq;
        g_sk[o] = kb[o] - km[o] * invk;
        g_sv[o] = vb[o] - vm[o] * invv;
        g_sp[o] = (pb[o] - pm[o]) * invp + pb2[o];
    }
}

// ---------------------------------------------------------------------------
// LIF on input x -> binary spikes xs (half). Chunked over CH_ batches.
// i indexes float4 within the chunk's [CH_ * C * N] region.
// ---------------------------------------------------------------------------
__global__ void lif_x_kernel(const float4* __restrict__ x4, int b0)
{
    int i = blockIdx.x * blockDim.x + threadIdx.x;
    if (i >= CH_ * C_ * N_ / 4) return;
    int off = b0 * C_ * N_ / 4;
    float4 v = make_float4(0.f, 0.f, 0.f, 0.f);
#pragma unroll
    for (int t = 0; t < T_; t++) {
        float4 xv = x4[t * (S_ / 4) + off + i];
        float4 s;
        v.x += (xv.x - v.x) * 0.5f; s.x = (v.x >= 1.f) ? 1.f : 0.f; v.x *= (1.f - s.x);
        v.y += (xv.y - v.y) * 0.5f; s.y = (v.y >= 1.f) ? 1.f : 0.f; v.y *= (1.f - s.y);
        v.z += (xv.z - v.z) * 0.5f; s.z = (v.z >= 1.f) ? 1.f : 0.f; v.z *= (1.f - s.z);
        v.w += (xv.w - v.w) * 0.5f; s.w = (v.w >= 1.f) ? 1.f : 0.f; v.w *= (1.f - s.w);
        __half2* o2 = reinterpret_cast<__half2*>(g_xs + t * S_) + 2 * (off + i);
        o2[0] = __floats2half2_rn(s.x, s.y);
        o2[1] = __floats2half2_rn(s.z, s.w);
    }
}

// ---------------------------------------------------------------------------
// Fused: LIF(q/k/v pre-act + BN shift) -> kv row-sum -> kv-LIF (v_th=0.5)
//        -> attn = q_spike * kv_spike (fp16). Chunked over CH_ batches.
// ---------------------------------------------------------------------------
__global__ void lif_attn_kernel(int b0)
{
    int gwl = (blockIdx.x * blockDim.x + threadIdx.x) >> 5;   // chunk-local b*C + c
    int lane = threadIdx.x & 31;
    if (gwl >= CH_ * C_) return;
    int gw = b0 * C_ + gwl;
    int c = gw & (C_ - 1);
    float shq = __ldg(&g_sq[c]);
    float shk = __ldg(&g_sk[c]);
    float shv = __ldg(&g_sv[c]);

    float vq[8], vk[8], vv[8];
#pragma unroll
    for (int e = 0; e < 8; e++) { vq[e] = 0.f; vk[e] = 0.f; vv[e] = 0.f; }
    float vkv = 0.f;

#pragma unroll
    for (int t = 0; t < T_; t++) {
        size_t base = (size_t)t * S_ + (size_t)gw * N_ + lane * 8;
        float4 q0 = *reinterpret_cast<const float4*>(g_q + base);
        float4 q1 = *reinterpret_cast<const float4*>(g_q + base + 4);
        float4 k0 = *reinterpret_cast<const float4*>(g_k + base);
        float4 k1 = *reinterpret_cast<const float4*>(g_k + base + 4);
        float4 v0 = *reinterpret_cast<const float4*>(g_v + base);
        float4 v1 = *reinterpret_cast<const float4*>(g_v + base + 4);
        float qp[8] = {q0.x, q0.y, q0.z, q0.w, q1.x, q1.y, q1.z, q1.w};
        float kp[8] = {k0.x, k0.y, k0.z, k0.w, k1.x, k1.y, k1.z, k1.w};
        float vp[8] = {v0.x, v0.y, v0.z, v0.w, v1.x, v1.y, v1.z, v1.w};

        float sq[8];
        float kvsum = 0.f;
#pragma unroll
        for (int e = 0; e < 8; e++) {
            float p, sk, sv;
            p = qp[e] + shq;
            vq[e] += (p - vq[e]) * 0.5f; sq[e] = (vq[e] >= 1.f) ? 1.f : 0.f; vq[e] *= (1.f - sq[e]);
            p = kp[e] + shk;
            vk[e] += (p - vk[e]) * 0.5f; sk = (vk[e] >= 1.f) ? 1.f : 0.f; vk[e] *= (1.f - sk);
            p = vp[e] + shv;
            vv[e] += (p - vv[e]) * 0.5f; sv = (vv[e] >= 1.f) ? 1.f : 0.f; vv[e] *= (1.f - sv);
            kvsum += sk * sv;
        }
#pragma unroll
        for (int off = 16; off > 0; off >>= 1)
            kvsum += __shfl_xor_sync(0xFFFFFFFFu, kvsum, off);

        vkv = vkv + (kvsum - vkv) * 0.5f;
        float skv = (vkv >= 0.5f) ? 1.f : 0.f;
        vkv = vkv * (1.f - skv);

        uint4 pk;
        __half2* ph = reinterpret_cast<__half2*>(&pk);
        ph[0] = __floats2half2_rn(sq[0] * skv, sq[1] * skv);
        ph[1] = __floats2half2_rn(sq[2] * skv, sq[3] * skv);
        ph[2] = __floats2half2_rn(sq[4] * skv, sq[5] * skv);
        ph[3] = __floats2half2_rn(sq[6] * skv, sq[7] * skv);
        *reinterpret_cast<uint4*>(g_attn + base) = pk;
    }
}

// ---------------------------------------------------------------------------
// fp16 GEMM (fp32 accumulate), block 128x128x32, 4 warps (64x64 warp tile),
// 2-stage cp.async. Chunked over CH_ batches.
// MODE 0: z in [0, 3*T_*CH_): which = z/16, r = z%16, tb = (r>>2)*B_ + b0 + (r&3).
//         A = folded fp16 weights, B = xs spikes; writes fp32 pre-activations.
// MODE 1: z in [0, T_*CH_): tb = (z>>2)*B_ + b0 + (z&3). A = proj weights,
//         B = attn; epilogue adds shift + identity, writes d_out.
// ---------------------------------------------------------------------------
template <int MODE>
__global__ void __launch_bounds__(128) gemm_kernel(const float* __restrict__ x_identity,
                                                   float* __restrict__ out_global, int b0)
{
    extern __shared__ __align__(16) char smemc[];
    __half* AsBase = reinterpret_cast<__half*>(smemc);              // [2][BM*ASTRH]
    __half* BsBase = AsBase + 2 * BM * ASTRH;                       // [2][BK*BSTRH]
    float* Cs = reinterpret_cast<float*>(smemc);                    // overlaps (after sync)

    int tid = threadIdx.x;
    int warp = tid >> 5;
    int wr = warp >> 1, wc = warp & 1;
    int n0 = blockIdx.x * BN;
    int o0 = blockIdx.y * BM;
    int z = blockIdx.z;

    const __half* A;
    const __half* Bsrc;
    float* Cdst = nullptr;
    const float* xid = nullptr;
    float* outp = nullptr;
    const float* shp = nullptr;

    if (MODE == 0) {
        int which = z >> 4;
        int r = z & 15;
        int tb = (r >> 2) * B_ + b0 + (r & 3);
        A = (which == 0) ? g_wq : (which == 1) ? g_wk : g_wv;
        Bsrc = g_xs + (size_t)tb * C_ * N_;
        Cdst = ((which == 0) ? g_q : (which == 1) ? g_k : g_v) + (size_t)tb * C_ * N_;
    } else {
        int tb = (z >> 2) * B_ + b0 + (z & 3);
        A = g_wp;
        shp = g_sp;
        Bsrc = g_attn + (size_t)tb * C_ * N_;
        xid = x_identity + (size_t)tb * C_ * N_;
        outp = out_global + (size_t)tb * C_ * N_;
    }

    wmma::fragment<wmma::accumulator, 16, 16, 16, float> acc[4][4];
#pragma unroll
    for (int i = 0; i < 4; i++)
#pragma unroll
        for (int j = 0; j < 4; j++)
            wmma::fill_fragment(acc[i][j], 0.0f);

    {
        __half* As = AsBase;
        __half* Bs = BsBase;
#pragma unroll
        for (int i = 0; i < 4; i++) {
            int idx = tid + i * 128;
            int r = idx >> 2, c8 = (idx & 3) << 3;
            cp16(&As[r * ASTRH + c8], &A[(o0 + r) * C_ + c8]);
        }
#pragma unroll
        for (int i = 0; i < 4; i++) {
            int idx = tid + i * 128;
            int r = idx >> 4, c8 = (idx & 15) << 3;
            cp16(&Bs[r * BSTRH + c8], &Bsrc[r * N_ + n0 + c8]);
        }
        CP_COMMIT();
    }

    int s = 0;
    for (int kt = 0; kt < C_; kt += BK, s ^= 1) {
        CP_WAIT0();
        __syncthreads();

        if (kt + BK < C_) {
            __half* As = AsBase + (s ^ 1) * BM * ASTRH;
            __half* Bs = BsBase + (s ^ 1) * BK * BSTRH;
            int ktn = kt + BK;
#pragma unroll
            for (int i = 0; i < 4; i++) {
                int idx = tid + i * 128;
                int r = idx >> 2, c8 = (idx & 3) << 3;
                cp16(&As[r * ASTRH + c8], &A[(o0 + r) * C_ + ktn + c8]);
            }
#pragma unroll
            for (int i = 0; i < 4; i++) {
                int idx = tid + i * 128;
                int r = idx >> 4, c8 = (idx & 15) << 3;
                cp16(&Bs[r * BSTRH + c8], &Bsrc[(ktn + r) * N_ + n0 + c8]);
            }
            CP_COMMIT();
        }

        const __half* As = AsBase + s * BM * ASTRH;
        const __half* Bs = BsBase + s * BK * BSTRH;
#pragma unroll
        for (int kk = 0; kk < BK; kk += 16) {
            wmma::fragment<wmma::matrix_a, 16, 16, 16, __half, wmma::row_major> af[4];
            wmma::fragment<wmma::matrix_b, 16, 16, 16, __half, wmma::row_major> bf[4];
#pragma unroll
            for (int i = 0; i < 4; i++)
                wmma::load_matrix_sync(af[i], &As[(wr * 64 + i * 16) * ASTRH + kk], ASTRH);
#pragma unroll
            for (int j = 0; j < 4; j++)
                wmma::load_matrix_sync(bf[j], &Bs[kk * BSTRH + wc * 64 + j * 16], BSTRH);
#pragma unroll
            for (int i = 0; i < 4; i++)
#pragma unroll
                for (int j = 0; j < 4; j++)
                    wmma::mma_sync(acc[i][j], af[i], bf[j], acc[i][j]);
        }
    }

    __syncthreads();
#pragma unroll
    for (int i = 0; i < 4; i++)
#pragma unroll
        for (int j = 0; j < 4; j++)
            wmma::store_matrix_sync(&Cs[(wr * 64 + i * 16) * CSTR + wc * 64 + j * 16],
                                    acc[i][j], CSTR, wmma::mem_row_major);
    __syncthreads();

    if (MODE == 0) {
#pragma unroll
        for (int e = 0; e < 32; e++) {
            int idx = tid + e * 128;
            int r = idx >> 5, c4 = (idx & 31) << 2;
            float4 cv = *reinterpret_cast<const float4*>(&Cs[r * CSTR + c4]);
            *reinterpret_cast<float4*>(&Cdst[(o0 + r) * N_ + n0 + c4]) = cv;
        }
    } else {
#pragma unroll
        for (int e = 0; e < 32; e++) {
            int idx = tid + e * 128;
            int r = idx >> 5, c4 = (idx & 31) << 2;
            int o = o0 + r;
            float4 cv = *reinterpret_cast<const float4*>(&Cs[r * CSTR + c4]);
            float4 xv = *reinterpret_cast<const float4*>(&xid[o * N_ + n0 + c4]);
            float sp = __ldg(&shp[o]);
            float4 res;
            res.x = cv.x + sp + xv.x;
            res.y = cv.y + sp + xv.y;
            res.z = cv.z + sp + xv.z;
            res.w = cv.w + sp + xv.w;
            *reinterpret_cast<float4*>(&outp[o * N_ + n0 + c4]) = res;
        }
    }
}

// ---------------------------------------------------------------------------
extern "C" void kernel_launch(void* const* d_in, const int* in_sizes, int n_in,
                              void* d_out, int out_size)
{
    const float* x    = (const float*)d_in[0];
    const float* q_w  = (const float*)d_in[1];
    const float* q_g  = (const float*)d_in[2];
    const float* q_b  = (const float*)d_in[3];
    const float* q_m  = (const float*)d_in[4];
    const float* q_v  = (const float*)d_in[5];
    const float* k_w  = (const float*)d_in[6];
    const float* k_g  = (const float*)d_in[7];
    const float* k_b  = (const float*)d_in[8];
    const float* k_m  = (const float*)d_in[9];
    const float* k_v  = (const float*)d_in[10];
    const float* v_w  = (const float*)d_in[11];
    const float* v_g  = (const float*)d_in[12];
    const float* v_b  = (const float*)d_in[13];
    const float* v_m  = (const float*)d_in[14];
    const float* v_v  = (const float*)d_in[15];
    const float* p_w  = (const float*)d_in[16];
    const float* p_b  = (const float*)d_in[17];
    const float* p_g  = (const float*)d_in[18];
    const float* p_b2 = (const float*)d_in[19];
    const float* p_m  = (const float*)d_in[20];
    const float* p_v  = (const float*)d_in[21];
    float* out = (float*)d_out;

    // One-time stream/event setup (host resources only; no device memory)
    static cudaStream_t s_tensor = nullptr, s_mem = nullptr;
    static cudaEvent_t eFork, eL[NCHUNK_], eG[NCHUNK_], eJoinM, eJoinT;
    if (s_tensor == nullptr) {
        cudaStreamCreateWithFlags(&s_tensor, cudaStreamNonBlocking);
        cudaStreamCreateWithFlags(&s_mem, cudaStreamNonBlocking);
        cudaEventCreateWithFlags(&eFork, cudaEventDisableTiming);
        for (int i = 0; i < NCHUNK_; i++) {
            cudaEventCreateWithFlags(&eL[i], cudaEventDisableTiming);
            cudaEventCreateWithFlags(&eG[i], cudaEventDisableTiming);
        }
        cudaEventCreateWithFlags(&eJoinM, cudaEventDisableTiming);
        cudaEventCreateWithFlags(&eJoinT, cudaEventDisableTiming);
        cudaFuncSetAttribute(gemm_kernel<0>, cudaFuncAttributeMaxDynamicSharedMemorySize, SMEM_BYTES);
        cudaFuncSetAttribute(gemm_kernel<1>, cudaFuncAttributeMaxDynamicSharedMemorySize, SMEM_BYTES);
    }

    // prep on base stream, then fork both worker streams off it
    prep_kernel<<<(C_ * C_ + 255) / 256, 256>>>(
        q_w, q_g, q_b, q_m, q_v,
        k_w, k_g, k_b, k_m, k_v,
        v_w, v_g, v_b, v_m, v_v,
        p_w, p_b, p_g, p_b2, p_m, p_v);
    cudaEventRecord(eFork, 0);
    cudaStreamWaitEvent(s_mem, eFork, 0);
    cudaStreamWaitEvent(s_tensor, eFork, 0);

    // s_mem: lif_x chunks (producers)
    for (int i = 0; i < NCHUNK_; i++) {
        lif_x_kernel<<<(CH_ * C_ * N_ / 4 + 255) / 256, 256, 0, s_mem>>>(
            reinterpret_cast<const float4*>(x), i * CH_);
        cudaEventRecord(eL[i], s_mem);
    }

    // s_tensor: qkv GEMM chunks
    for (int i = 0; i < NCHUNK_; i++) {
        cudaStreamWaitEvent(s_tensor, eL[i], 0);
        gemm_kernel<0><<<dim3(N_ / BN, C_ / BM, 3 * T_ * CH_), 128, SMEM_BYTES, s_tensor>>>(
            nullptr, nullptr, i * CH_);
        cudaEventRecord(eG[i], s_tensor);
    }

    // s_mem: lif_attn + proj chunks (consume GEMM-0 results as they finish)
    for (int i = 0; i < NCHUNK_; i++) {
        cudaStreamWaitEvent(s_mem, eG[i], 0);
        lif_attn_kernel<<<(CH_ * C_ * 32 + 255) / 256, 256, 0, s_mem>>>(i * CH_);
        gemm_kernel<1><<<dim3(N_ / BN, C_ / BM, T_ * CH_), 128, SMEM_BYTES, s_mem>>>(
            x, out, i * CH_);
    }

    // join both streams back into the base stream
    cudaEventRecord(eJoinM, s_mem);
    cudaEventRecord(eJoinT, s_tensor);
    cudaStreamWaitEvent(0, eJoinM, 0);
    cudaStreamWaitEvent(0, eJoinT, 0);
}

// round 14
// speedup vs baseline: 1.1397x; 1.1397x over previous
#include <cuda_runtime.h>
#include <cuda_fp16.h>
#include <mma.h>

using namespace nvcuda;

// Problem constants
constexpr int T_ = 4;
constexpr int B_ = 16;
constexpr int C_ = 512;
constexpr int N_ = 256;                // H*W
constexpr int S_ = B_ * C_ * N_;       // per-timestep elements
constexpr int TOT_ = T_ * S_;

// GEMM tiling: block 128x128x32, 4 warps, warp tile 64x64, fp16 operands
constexpr int BM = 128, BN = 128, BK = 32;
constexpr int ASTRH = 40;    // half stride; 80B = 5*16
constexpr int BSTRH = 136;   // 272B = 17*16
constexpr int CSTR = 132;    // float stride for epilogue staging
constexpr int PIPE_BYTES = 2 * (BM * ASTRH + BK * BSTRH) * 2;
constexpr int EPI_BYTES = BM * CSTR * 4;
constexpr int SMEM_BYTES = (PIPE_BYTES > EPI_BYTES) ? PIPE_BYTES : EPI_BYTES;

// Scratch (device globals: allocation-free rule)
__device__ __align__(16) __half g_wq[C_ * C_];
__device__ __align__(16) __half g_wk[C_ * C_];
__device__ __align__(16) __half g_wv[C_ * C_];
__device__ __align__(16) __half g_wp[C_ * C_];
__device__ float g_sq[C_];
__device__ float g_sk[C_];
__device__ float g_sv[C_];
__device__ float g_sp[C_];
__device__ __align__(16) __half g_xs[TOT_];          // input spikes
__device__ __align__(16) float g_q[TOT_];            // q pre-activations (fp32)
__device__ __align__(16) float g_k[TOT_];
__device__ __align__(16) float g_v[TOT_];
__device__ __align__(16) __half g_attn[TOT_];        // attn = q_spike * kv_spike (fp16)

// ---------------------------------------------------------------------------
// cp.async helpers
// ---------------------------------------------------------------------------
__device__ __forceinline__ void cp16(void* dst, const void* src) {
    unsigned s = (unsigned)__cvta_generic_to_shared(dst);
    asm volatile("cp.async.cg.shared.global [%0], [%1], 16;\n" :: "r"(s), "l"(src));
}
#define CP_COMMIT() asm volatile("cp.async.commit_group;\n" ::: "memory")
#define CP_WAIT0()  asm volatile("cp.async.wait_group 0;\n" ::: "memory")

// ---------------------------------------------------------------------------
// Prep: fold BN scale into weights (fp16); per-channel shifts (fp32).
// ---------------------------------------------------------------------------
__global__ void prep_kernel(
    const float* __restrict__ qw, const float* __restrict__ qg, const float* __restrict__ qb,
    const float* __restrict__ qm, const float* __restrict__ qvv,
    const float* __restrict__ kw, const float* __restrict__ kg, const float* __restrict__ kb,
    const float* __restrict__ km, const float* __restrict__ kvv,
    const float* __restrict__ vw, const float* __restrict__ vg, const float* __restrict__ vb,
    const float* __restrict__ vm, const float* __restrict__ vvv,
    const float* __restrict__ pw, const float* __restrict__ pb, const float* __restrict__ pg,
    const float* __restrict__ pb2, const float* __restrict__ pm, const float* __restrict__ pvv)
{
    int idx = blockIdx.x * blockDim.x + threadIdx.x;
    if (idx >= C_ * C_) return;
    int o = idx >> 9;
    float invq = qg[o] / sqrtf(qvv[o] + 1e-5f);
    float invk = kg[o] / sqrtf(kvv[o] + 1e-5f);
    float invv = vg[o] / sqrtf(vvv[o] + 1e-5f);
    float invp = pg[o] / sqrtf(pvv[o] + 1e-5f);
    g_wq[idx] = __float2half_rn(qw[idx] * invq);
    g_wk[idx] = __float2half_rn(kw[idx] * invk);
    g_wv[idx] = __float2half_rn(vw[idx] * invv);
    g_wp[idx] = __float2half_rn(pw[idx] * invp);
    if ((idx & 511) == 0) {
        g_sq[o] = qb[o] - qm[o] * invq;
        g_sk[o] = kb[o] - km[o] * invk;
        g_sv[o] = vb[o] - vm[o] * invv;
        g_sp[o] = (pb[o] - pm[o]) * invp + pb2[o];
    }
}

// ---------------------------------------------------------------------------
// LIF on input x -> binary spikes xs (half). All 4 t-loads hoisted (MLP=4).
// ---------------------------------------------------------------------------
__global__ void lif_x_kernel(const float4* __restrict__ x4)
{
    int i = blockIdx.x * blockDim.x + threadIdx.x;
    if (i >= S_ / 4) return;
    float4 xv[T_];
#pragma unroll
    for (int t = 0; t < T_; t++) xv[t] = x4[t * (S_ / 4) + i];

    float4 v = make_float4(0.f, 0.f, 0.f, 0.f);
#pragma unroll
    for (int t = 0; t < T_; t++) {
        float4 s;
        v.x += (xv[t].x - v.x) * 0.5f; s.x = (v.x >= 1.f) ? 1.f : 0.f; v.x *= (1.f - s.x);
        v.y += (xv[t].y - v.y) * 0.5f; s.y = (v.y >= 1.f) ? 1.f : 0.f; v.y *= (1.f - s.y);
        v.z += (xv[t].z - v.z) * 0.5f; s.z = (v.z >= 1.f) ? 1.f : 0.f; v.z *= (1.f - s.z);
        v.w += (xv[t].w - v.w) * 0.5f; s.w = (v.w >= 1.f) ? 1.f : 0.f; v.w *= (1.f - s.w);
        __half2* o2 = reinterpret_cast<__half2*>(g_xs + t * S_) + 2 * i;
        o2[0] = __floats2half2_rn(s.x, s.y);
        o2[1] = __floats2half2_rn(s.z, s.w);
    }
}

// ---------------------------------------------------------------------------
// Fused: LIF(q/k/v pre-act + BN shift) -> kv row-sum -> kv-LIF (v_th=0.5)
//        -> attn = q_spike * kv_spike (fp16).
// One warp per (b,c) row; 8 elems/lane; t+1 loads double-buffered.
// ---------------------------------------------------------------------------
__global__ void lif_attn_kernel()
{
    int gw = (blockIdx.x * blockDim.x + threadIdx.x) >> 5;   // b*C + c
    int lane = threadIdx.x & 31;
    if (gw >= B_ * C_) return;
    int c = gw & (C_ - 1);
    float shq = __ldg(&g_sq[c]);
    float shk = __ldg(&g_sk[c]);
    float shv = __ldg(&g_sv[c]);

    float vq[8], vk[8], vv[8];
#pragma unroll
    for (int e = 0; e < 8; e++) { vq[e] = 0.f; vk[e] = 0.f; vv[e] = 0.f; }
    float vkv = 0.f;

    size_t base0 = (size_t)gw * N_ + lane * 8;

    // double-buffered loads: buf[parity][0..1] for q/k/v
    float4 bq[2][2], bk[2][2], bv[2][2];
    bq[0][0] = *reinterpret_cast<const float4*>(g_q + base0);
    bq[0][1] = *reinterpret_cast<const float4*>(g_q + base0 + 4);
    bk[0][0] = *reinterpret_cast<const float4*>(g_k + base0);
    bk[0][1] = *reinterpret_cast<const float4*>(g_k + base0 + 4);
    bv[0][0] = *reinterpret_cast<const float4*>(g_v + base0);
    bv[0][1] = *reinterpret_cast<const float4*>(g_v + base0 + 4);

#pragma unroll
    for (int t = 0; t < T_; t++) {
        int cur = t & 1;
        if (t + 1 < T_) {
            int nxt = (t + 1) & 1;
            size_t nb = (size_t)(t + 1) * S_ + base0;
            bq[nxt][0] = *reinterpret_cast<const float4*>(g_q + nb);
            bq[nxt][1] = *reinterpret_cast<const float4*>(g_q + nb + 4);
            bk[nxt][0] = *reinterpret_cast<const float4*>(g_k + nb);
            bk[nxt][1] = *reinterpret_cast<const float4*>(g_k + nb + 4);
            bv[nxt][0] = *reinterpret_cast<const float4*>(g_v + nb);
            bv[nxt][1] = *reinterpret_cast<const float4*>(g_v + nb + 4);
        }
        float qp[8] = {bq[cur][0].x, bq[cur][0].y, bq[cur][0].z, bq[cur][0].w,
                       bq[cur][1].x, bq[cur][1].y, bq[cur][1].z, bq[cur][1].w};
        float kp[8] = {bk[cur][0].x, bk[cur][0].y, bk[cur][0].z, bk[cur][0].w,
                       bk[cur][1].x, bk[cur][1].y, bk[cur][1].z, bk[cur][1].w};
        float vp[8] = {bv[cur][0].x, bv[cur][0].y, bv[cur][0].z, bv[cur][0].w,
                       bv[cur][1].x, bv[cur][1].y, bv[cur][1].z, bv[cur][1].w};

        float sq[8];
        float kvsum = 0.f;
#pragma unroll
        for (int e = 0; e < 8; e++) {
            float p, sk, sv;
            p = qp[e] + shq;
            vq[e] += (p - vq[e]) * 0.5f; sq[e] = (vq[e] >= 1.f) ? 1.f : 0.f; vq[e] *= (1.f - sq[e]);
            p = kp[e] + shk;
            vk[e] += (p - vk[e]) * 0.5f; sk = (vk[e] >= 1.f) ? 1.f : 0.f; vk[e] *= (1.f - sk);
            p = vp[e] + shv;
            vv[e] += (p - vv[e]) * 0.5f; sv = (vv[e] >= 1.f) ? 1.f : 0.f; vv[e] *= (1.f - sv);
            kvsum += sk * sv;
        }
#pragma unroll
        for (int off = 16; off > 0; off >>= 1)
            kvsum += __shfl_xor_sync(0xFFFFFFFFu, kvsum, off);

        vkv = vkv + (kvsum - vkv) * 0.5f;
        float skv = (vkv >= 0.5f) ? 1.f : 0.f;
        vkv = vkv * (1.f - skv);

        uint4 pk;
        __half2* ph = reinterpret_cast<__half2*>(&pk);
        ph[0] = __floats2half2_rn(sq[0] * skv, sq[1] * skv);
        ph[1] = __floats2half2_rn(sq[2] * skv, sq[3] * skv);
        ph[2] = __floats2half2_rn(sq[4] * skv, sq[5] * skv);
        ph[3] = __floats2half2_rn(sq[6] * skv, sq[7] * skv);
        *reinterpret_cast<uint4*>(g_attn + (size_t)t * S_ + base0) = pk;
    }
}

// ---------------------------------------------------------------------------
// fp16 GEMM (fp32 accumulate), block 128x128x32, 4 warps (64x64 warp tile),
// 2-stage cp.async.
// MODE 0: z = which*64 + tb.  A = folded fp16 weights, B = xs spikes,
//         writes fp32 pre-activations to g_q/g_k/g_v.
// MODE 1: z = tb. A = proj weights, B = attn; epilogue adds shift + identity,
//         writes d_out.
// ---------------------------------------------------------------------------
template <int MODE>
__global__ void __launch_bounds__(128) gemm_kernel(const float* __restrict__ x_identity,
                                                   float* __restrict__ out_global)
{
    extern __shared__ __align__(16) char smemc[];
    __half* AsBase = reinterpret_cast<__half*>(smemc);              // [2][BM*ASTRH]
    __half* BsBase = AsBase + 2 * BM * ASTRH;                       // [2][BK*BSTRH]
    float* Cs = reinterpret_cast<float*>(smemc);                    // overlaps (after sync)

    int tid = threadIdx.x;
    int warp = tid >> 5;
    int wr = warp >> 1, wc = warp & 1;
    int n0 = blockIdx.x * BN;
    int o0 = blockIdx.y * BM;
    int z = blockIdx.z;

    const __half* A;
    const __half* Bsrc;
    float* Cdst = nullptr;
    const float* xid = nullptr;
    float* outp = nullptr;
    const float* shp = nullptr;

    if (MODE == 0) {
        int which = z >> 6;
        int tb = z & 63;
        A = (which == 0) ? g_wq : (which == 1) ? g_wk : g_wv;
        Bsrc = g_xs + (size_t)tb * C_ * N_;
        Cdst = ((which == 0) ? g_q : (which == 1) ? g_k : g_v) + (size_t)tb * C_ * N_;
    } else {
        A = g_wp;
        shp = g_sp;
        Bsrc = g_attn + (size_t)z * C_ * N_;
        xid = x_identity + (size_t)z * C_ * N_;
        outp = out_global + (size_t)z * C_ * N_;
    }

    wmma::fragment<wmma::accumulator, 16, 16, 16, float> acc[4][4];
#pragma unroll
    for (int i = 0; i < 4; i++)
#pragma unroll
        for (int j = 0; j < 4; j++)
            wmma::fill_fragment(acc[i][j], 0.0f);

    {
        __half* As = AsBase;
        __half* Bs = BsBase;
#pragma unroll
        for (int i = 0; i < 4; i++) {
            int idx = tid + i * 128;
            int r = idx >> 2, c8 = (idx & 3) << 3;
            cp16(&As[r * ASTRH + c8], &A[(o0 + r) * C_ + c8]);
        }
#pragma unroll
        for (int i = 0; i < 4; i++) {
            int idx = tid + i * 128;
            int r = idx >> 4, c8 = (idx & 15) << 3;
            cp16(&Bs[r * BSTRH + c8], &Bsrc[r * N_ + n0 + c8]);
        }
        CP_COMMIT();
    }

    int s = 0;
    for (int kt = 0; kt < C_; kt += BK, s ^= 1) {
        CP_WAIT0();
        __syncthreads();

        if (kt + BK < C_) {
            __half* As = AsBase + (s ^ 1) * BM * ASTRH;
            __half* Bs = BsBase + (s ^ 1) * BK * BSTRH;
            int ktn = kt + BK;
#pragma unroll
            for (int i = 0; i < 4; i++) {
                int idx = tid + i * 128;
                int r = idx >> 2, c8 = (idx & 3) << 3;
                cp16(&As[r * ASTRH + c8], &A[(o0 + r) * C_ + ktn + c8]);
            }
#pragma unroll
            for (int i = 0; i < 4; i++) {
                int idx = tid + i * 128;
                int r = idx >> 4, c8 = (idx & 15) << 3;
                cp16(&Bs[r * BSTRH + c8], &Bsrc[(ktn + r) * N_ + n0 + c8]);
            }
            CP_COMMIT();
        }

        const __half* As = AsBase + s * BM * ASTRH;
        const __half* Bs = BsBase + s * BK * BSTRH;
#pragma unroll
        for (int kk = 0; kk < BK; kk += 16) {
            wmma::fragment<wmma::matrix_a, 16, 16, 16, __half, wmma::row_major> af[4];
            wmma::fragment<wmma::matrix_b, 16, 16, 16, __half, wmma::row_major> bf[4];
#pragma unroll
            for (int i = 0; i < 4; i++)
                wmma::load_matrix_sync(af[i], &As[(wr * 64 + i * 16) * ASTRH + kk], ASTRH);
#pragma unroll
            for (int j = 0; j < 4; j++)
                wmma::load_matrix_sync(bf[j], &Bs[kk * BSTRH + wc * 64 + j * 16], BSTRH);
#pragma unroll
            for (int i = 0; i < 4; i++)
#pragma unroll
                for (int j = 0; j < 4; j++)
                    wmma::mma_sync(acc[i][j], af[i], bf[j], acc[i][j]);
        }
    }

    __syncthreads();
#pragma unroll
    for (int i = 0; i < 4; i++)
#pragma unroll
        for (int j = 0; j < 4; j++)
            wmma::store_matrix_sync(&Cs[(wr * 64 + i * 16) * CSTR + wc * 64 + j * 16],
                                    acc[i][j], CSTR, wmma::mem_row_major);
    __syncthreads();

    if (MODE == 0) {
#pragma unroll
        for (int e = 0; e < 32; e++) {
            int idx = tid + e * 128;
            int r = idx >> 5, c4 = (idx & 31) << 2;
            float4 cv = *reinterpret_cast<const float4*>(&Cs[r * CSTR + c4]);
            *reinterpret_cast<float4*>(&Cdst[(o0 + r) * N_ + n0 + c4]) = cv;
        }
    } else {
#pragma unroll
        for (int e = 0; e < 32; e++) {
            int idx = tid + e * 128;
            int r = idx >> 5, c4 = (idx & 31) << 2;
            int o = o0 + r;
            float4 cv = *reinterpret_cast<const float4*>(&Cs[r * CSTR + c4]);
            float4 xv = *reinterpret_cast<const float4*>(&xid[o * N_ + n0 + c4]);
            float sp = __ldg(&shp[o]);
            float4 res;
            res.x = cv.x + sp + xv.x;
            res.y = cv.y + sp + xv.y;
            res.z = cv.z + sp + xv.z;
            res.w = cv.w + sp + xv.w;
            *reinterpret_cast<float4*>(&outp[o * N_ + n0 + c4]) = res;
        }
    }
}

// ---------------------------------------------------------------------------
extern "C" void kernel_launch(void* const* d_in, const int* in_sizes, int n_in,
                              void* d_out, int out_size)
{
    const float* x    = (const float*)d_in[0];
    const float* q_w  = (const float*)d_in[1];
    const float* q_g  = (const float*)d_in[2];
    const float* q_b  = (const float*)d_in[3];
    const float* q_m  = (const float*)d_in[4];
    const float* q_v  = (const float*)d_in[5];
    const float* k_w  = (const float*)d_in[6];
    const float* k_g  = (const float*)d_in[7];
    const float* k_b  = (const float*)d_in[8];
    const float* k_m  = (const float*)d_in[9];
    const float* k_v  = (const float*)d_in[10];
    const float* v_w  = (const float*)d_in[11];
    const float* v_g  = (const float*)d_in[12];
    const float* v_b  = (const float*)d_in[13];
    const float* v_m  = (const float*)d_in[14];
    const float* v_v  = (const float*)d_in[15];
    const float* p_w  = (const float*)d_in[16];
    const float* p_b  = (const float*)d_in[17];
    const float* p_g  = (const float*)d_in[18];
    const float* p_b2 = (const float*)d_in[19];
    const float* p_m  = (const float*)d_in[20];
    const float* p_v  = (const float*)d_in[21];
    float* out = (float*)d_out;

    cudaFuncSetAttribute(gemm_kernel<0>, cudaFuncAttributeMaxDynamicSharedMemorySize, SMEM_BYTES);
    cudaFuncSetAttribute(gemm_kernel<1>, cudaFuncAttributeMaxDynamicSharedMemorySize, SMEM_BYTES);

    prep_kernel<<<(C_ * C_ + 255) / 256, 256>>>(
        q_w, q_g, q_b, q_m, q_v,
        k_w, k_g, k_b, k_m, k_v,
        v_w, v_g, v_b, v_m, v_v,
        p_w, p_b, p_g, p_b2, p_m, p_v);

    lif_x_kernel<<<(S_ / 4 + 255) / 256, 256>>>(reinterpret_cast<const float4*>(x));

    // MODE 0: q/k/v convs (fp32 pre-activations)
    gemm_kernel<0><<<dim3(N_ / BN, C_ / BM, 3 * T_ * B_), 128, SMEM_BYTES>>>(nullptr, nullptr);

    // Fused LIF(q/k/v) + kv reduction + kv-LIF + attn gating -> g_attn
    lif_attn_kernel<<<(B_ * C_ * 32 + 255) / 256, 256>>>();

    // MODE 1: proj conv on attn + BN + bias + identity
    gemm_kernel<1><<<dim3(N_ / BN, C_ / BM, T_ * B_), 128, SMEM_BYTES>>>(x, out);
}